// round 12
// baseline (speedup 1.0000x reference)
#include <cuda_runtime.h>
#include <cuda_fp16.h>

#define HD 64
static const int NMAX = 100000;
static const int EMAX = 1200000;

// Scratch (allocation-free per harness rules)
__device__ int    g_deg[NMAX];
__device__ int    g_off[NMAX + 1];
__device__ int    g_cur[NMAX];
__device__ int    g_part[1024];
__device__ int    g_csr[EMAX];
__device__ float  g_dinv[NMAX];
__device__ __half g_sh[NMAX * HD];    // fp16 layer-1 messages; dinv folded in by k_scale_sh
__device__ __half g_sh2[NMAX * HD];   // fp16 layer-2 messages; dinv folded at store

// ---------- packed f32x2 helpers ----------
__device__ __forceinline__ unsigned long long pack2(float a) {
    unsigned long long r;
    asm("mov.b64 %0, {%1, %1};" : "=l"(r) : "f"(a));
    return r;
}
__device__ __forceinline__ void fma2(unsigned long long& d,
                                     unsigned long long a,
                                     unsigned long long b) {
    asm("fma.rn.f32x2 %0, %1, %2, %0;" : "+l"(d) : "l"(a), "l"(b));
}
__device__ __forceinline__ float2 unpack2(unsigned long long v) {
    float2 u;
    asm("mov.b64 {%0, %1}, %2;" : "=f"(u.x), "=f"(u.y) : "l"(v));
    return u;
}

// ---------- graph preprocessing (branch A, overlapped) ----------
__global__ void k_zero_deg(int n) {
    int i = blockIdx.x * blockDim.x + threadIdx.x;
    if (i < n) g_deg[i] = 0;
}

__global__ void k_count(const int* __restrict__ dst, int e) {
    int i = blockIdx.x * blockDim.x + threadIdx.x;
    if (i < e) {
        int d = dst[i];
        if (d >= 0 && d < NMAX) atomicAdd(&g_deg[d], 1);
    }
}

#define SCAN_B 512
__global__ __launch_bounds__(SCAN_B) void k_scan1(int n) {
    __shared__ int warp_sums[SCAN_B / 32];
    int i = blockIdx.x * SCAN_B + threadIdx.x;
    int v = (i < n) ? g_deg[i] : 0;
    int lane = threadIdx.x & 31, wid = threadIdx.x >> 5;

    int s = v;
    #pragma unroll
    for (int d = 1; d < 32; d <<= 1) {
        int t = __shfl_up_sync(0xffffffffu, s, d);
        if (lane >= d) s += t;
    }
    if (lane == 31) warp_sums[wid] = s;
    __syncthreads();
    if (wid == 0) {
        int ws = (lane < SCAN_B / 32) ? warp_sums[lane] : 0;
        #pragma unroll
        for (int d = 1; d < SCAN_B / 32; d <<= 1) {
            int t = __shfl_up_sync(0xffffffffu, ws, d);
            if (lane >= d) ws += t;
        }
        if (lane < SCAN_B / 32) warp_sums[lane] = ws;
    }
    __syncthreads();
    int base = (wid > 0) ? warp_sums[wid - 1] : 0;
    int incl = base + s;
    if (i < n) g_off[i] = incl - v;
    if (threadIdx.x == SCAN_B - 1) g_part[blockIdx.x] = incl;
}

// fused pass 2+3: reduce g_part[0..blockIdx) inline, finalize offsets/cursors/dinv
__global__ __launch_bounds__(SCAN_B) void k_scan3(int n, int e) {
    __shared__ int warp_red[SCAN_B / 32];
    __shared__ int s_base;
    int b = blockIdx.x;
    int tid = threadIdx.x, lane = tid & 31, wid = tid >> 5;

    int v = (tid < b) ? g_part[tid] : 0;
    #pragma unroll
    for (int d = 16; d > 0; d >>= 1) v += __shfl_down_sync(0xffffffffu, v, d);
    if (lane == 0) warp_red[wid] = v;
    __syncthreads();
    if (wid == 0) {
        int t = (lane < SCAN_B / 32) ? warp_red[lane] : 0;
        #pragma unroll
        for (int d = 8; d > 0; d >>= 1) t += __shfl_down_sync(0xffffffffu, t, d);
        if (lane == 0) s_base = t;
    }
    __syncthreads();
    int base = s_base;

    int i = b * SCAN_B + tid;
    if (i < n) {
        int o = g_off[i] + base;
        g_off[i] = o;
        g_cur[i] = o;
        g_dinv[i] = rsqrtf((float)(g_deg[i] + 1));
    }
    if (i == 0) g_off[n] = e;
}

__global__ void k_fill(const int* __restrict__ src, const int* __restrict__ dst, int e) {
    int i = blockIdx.x * blockDim.x + threadIdx.x;
    if (i < e) {
        int d = dst[i];
        if (d >= 0 && d < NMAX) {
            int pos = atomicAdd(&g_cur[d], 1);
            if (pos >= 0 && pos < EMAX) g_csr[pos] = src[i];
        }
    }
}

// ---------- helpers ----------
#define SXS 68   // padded row stride for sX

__device__ __forceinline__ float4 ld_half4(const __half* base, int u, int c) {
    uint2 p = *reinterpret_cast<const uint2*>(&base[(size_t)u * HD + c]);
    __half2 a = *reinterpret_cast<__half2*>(&p.x);
    __half2 b = *reinterpret_cast<__half2*>(&p.y);
    float2 fa = __half22float2(a), fb = __half22float2(b);
    return make_float4(fa.x, fa.y, fb.x, fb.y);
}

// 4x8 tile GEMM: sX[64x64 fp32, stride SXS] @ sW[64x64] -> acc[4 rows][4 col-pairs]
// 128 threads: tx = t&7 (col octet), ty = t>>3 (row quad)
__device__ __forceinline__ void gemm_tile8(const float* sX, const float* sW,
                                           unsigned long long acc[4][4],
                                           int tx, int ty) {
    #pragma unroll 8
    for (int k = 0; k < 64; k++) {
        ulonglong2 w0 = *reinterpret_cast<const ulonglong2*>(&sW[k * 64 + tx * 8]);
        ulonglong2 w1 = *reinterpret_cast<const ulonglong2*>(&sW[k * 64 + tx * 8 + 4]);
        #pragma unroll
        for (int i = 0; i < 4; i++) {
            unsigned long long ap = pack2(sX[(ty * 4 + i) * SXS + k]);
            fma2(acc[i][0], ap, w0.x);
            fma2(acc[i][1], ap, w0.y);
            fma2(acc[i][2], ap, w1.x);
            fma2(acc[i][3], ap, w1.y);
        }
    }
}

// store 8 accum cols as fp16 (optionally scaled) at g[r*64 + tx*8]
__device__ __forceinline__ void store_half8(__half* base, int r, int tx,
                                            const unsigned long long* a, float s) {
    float2 p0 = unpack2(a[0]), p1 = unpack2(a[1]);
    float2 p2 = unpack2(a[2]), p3 = unpack2(a[3]);
    __half2 h0 = __floats2half2_rn(p0.x * s, p0.y * s);
    __half2 h1 = __floats2half2_rn(p1.x * s, p1.y * s);
    __half2 h2 = __floats2half2_rn(p2.x * s, p2.y * s);
    __half2 h3 = __floats2half2_rn(p3.x * s, p3.y * s);
    uint4 o;
    o.x = *reinterpret_cast<unsigned int*>(&h0);
    o.y = *reinterpret_cast<unsigned int*>(&h1);
    o.z = *reinterpret_cast<unsigned int*>(&h2);
    o.w = *reinterpret_cast<unsigned int*>(&h3);
    *reinterpret_cast<uint4*>(&base[(size_t)r * HD + tx * 8]) = o;
}

// ---------- fused: (x @ W_pre + b_pre) -> ori_x ; tile @ W1 -> g_sh ----------
__global__ __launch_bounds__(128) void k_fused_pre_w1(
    const float* __restrict__ x, const float* __restrict__ Wp,
    const float* __restrict__ bp, const float* __restrict__ W1,
    float* __restrict__ ori_x, int n)
{
    __shared__ float sX[64 * SXS];
    __shared__ float sW[64 * 64];
    int row0 = blockIdx.x * 64;
    int t = threadIdx.x;
    int tx = t & 7, ty = t >> 3;

    unsigned long long acc[4][4] = {};

    for (int kc = 0; kc < 2; kc++) {
        if (kc) __syncthreads();
        #pragma unroll
        for (int it = 0; it < 8; it++) {
            int idx = t + it * 128;
            int r = idx >> 4, c4 = idx & 15;
            float4 v = make_float4(0.f, 0.f, 0.f, 0.f);
            if (row0 + r < n)
                v = *reinterpret_cast<const float4*>(&x[(size_t)(row0 + r) * 128 + kc * 64 + c4 * 4]);
            *reinterpret_cast<float4*>(&sX[r * SXS + c4 * 4]) = v;
            *reinterpret_cast<float4*>(&sW[r * 64 + c4 * 4]) =
                *reinterpret_cast<const float4*>(&Wp[(size_t)(kc * 64 + r) * 64 + c4 * 4]);
        }
        __syncthreads();
        gemm_tile8(sX, sW, acc, tx, ty);
    }

    // epilogue 1: +bias, write ori_x, park tile in sX, load W1
    __syncthreads();
    float4 bb0 = *reinterpret_cast<const float4*>(&bp[tx * 8]);
    float4 bb1 = *reinterpret_cast<const float4*>(&bp[tx * 8 + 4]);
    #pragma unroll
    for (int i = 0; i < 4; i++) {
        float2 p0 = unpack2(acc[i][0]), p1 = unpack2(acc[i][1]);
        float2 p2 = unpack2(acc[i][2]), p3 = unpack2(acc[i][3]);
        float4 o0 = make_float4(p0.x + bb0.x, p0.y + bb0.y, p1.x + bb0.z, p1.y + bb0.w);
        float4 o1 = make_float4(p2.x + bb1.x, p2.y + bb1.y, p3.x + bb1.z, p3.y + bb1.w);
        int lr = ty * 4 + i;
        *reinterpret_cast<float4*>(&sX[lr * SXS + tx * 8]) = o0;
        *reinterpret_cast<float4*>(&sX[lr * SXS + tx * 8 + 4]) = o1;
        int r = row0 + lr;
        if (r < n) {
            *reinterpret_cast<float4*>(&ori_x[(size_t)r * HD + tx * 8]) = o0;
            *reinterpret_cast<float4*>(&ori_x[(size_t)r * HD + tx * 8 + 4]) = o1;
        }
    }
    #pragma unroll
    for (int it = 0; it < 8; it++) {
        int idx = t + it * 128;
        int r = idx >> 4, c4 = idx & 15;
        *reinterpret_cast<float4*>(&sW[r * 64 + c4 * 4]) =
            *reinterpret_cast<const float4*>(&W1[(size_t)r * 64 + c4 * 4]);
    }
    __syncthreads();

    // phase 2: g_sh = tile @ W1 (fp16, unscaled — dinv folded later by k_scale_sh)
    unsigned long long acc2[4][4] = {};
    gemm_tile8(sX, sW, acc2, tx, ty);
    #pragma unroll
    for (int i = 0; i < 4; i++) {
        int r = row0 + ty * 4 + i;
        if (r < n) store_half8(g_sh, r, tx, acc2[i], 1.0f);
    }
}

// ---------- fold dinv into g_sh in place (after join) ----------
__global__ void k_scale_sh(int n) {
    int i = blockIdx.x * blockDim.x + threadIdx.x;   // one uint2 (4 halfs) each
    if (i >= n * (HD / 4)) return;
    int v = i >> 4;
    float d = g_dinv[v];
    uint2 p = *reinterpret_cast<uint2*>(&g_sh[(size_t)i * 4]);
    __half2 a = *reinterpret_cast<__half2*>(&p.x);
    __half2 b = *reinterpret_cast<__half2*>(&p.y);
    float2 fa = __half22float2(a), fb = __half22float2(b);
    __half2 h0 = __floats2half2_rn(fa.x * d, fa.y * d);
    __half2 h1 = __floats2half2_rn(fb.x * d, fb.y * d);
    uint2 o;
    o.x = *reinterpret_cast<unsigned int*>(&h0);
    o.y = *reinterpret_cast<unsigned int*>(&h1);
    *reinterpret_cast<uint2*>(&g_sh[(size_t)i * 4]) = o;
}

// ---------- fused: gather layer-1 -> h (smem) ; h @ W2 -> g_sh2 (dinv-scaled) ----------
__global__ __launch_bounds__(128) void k_fused_gather_w2(
    const float* __restrict__ b1, const float* __restrict__ W2, int n)
{
    __shared__ float sX[64 * SXS];
    __shared__ float sW[64 * 64];
    int row0 = blockIdx.x * 64;
    int t = threadIdx.x;
    int tx = t & 7, ty = t >> 3;
    int grp = t >> 4;              // 8 groups of 16 threads
    int c = (t & 15) * 4;

    float4 bb1 = *reinterpret_cast<const float4*>(&b1[c]);
    #pragma unroll
    for (int it = 0; it < 8; it++) {
        int lr = grp + it * 8;
        int v = row0 + lr;
        float4 h = make_float4(0.f, 0.f, 0.f, 0.f);
        if (v < n) {
            int beg = g_off[v];
            int end = g_off[v + 1];
            float dv = g_dinv[v];
            float4 acc = ld_half4(g_sh, v, c);    // self-loop (already dinv[v]-scaled)

            int j = beg;
            for (; j + 4 <= end; j += 4) {
                int u0 = __ldg(&g_csr[j]);
                int u1 = __ldg(&g_csr[j + 1]);
                int u2 = __ldg(&g_csr[j + 2]);
                int u3 = __ldg(&g_csr[j + 3]);
                float4 a0 = ld_half4(g_sh, u0, c);
                float4 a1 = ld_half4(g_sh, u1, c);
                float4 a2 = ld_half4(g_sh, u2, c);
                float4 a3 = ld_half4(g_sh, u3, c);
                acc.x += (a0.x + a1.x) + (a2.x + a3.x);
                acc.y += (a0.y + a1.y) + (a2.y + a3.y);
                acc.z += (a0.z + a1.z) + (a2.z + a3.z);
                acc.w += (a0.w + a1.w) + (a2.w + a3.w);
            }
            for (; j < end; j++) {
                int u = __ldg(&g_csr[j]);
                float4 a = ld_half4(g_sh, u, c);
                acc.x += a.x; acc.y += a.y; acc.z += a.z; acc.w += a.w;
            }
            h.x = fmaxf(fmaf(dv, acc.x, bb1.x), 0.f);
            h.y = fmaxf(fmaf(dv, acc.y, bb1.y), 0.f);
            h.z = fmaxf(fmaf(dv, acc.z, bb1.z), 0.f);
            h.w = fmaxf(fmaf(dv, acc.w, bb1.w), 0.f);
        }
        *reinterpret_cast<float4*>(&sX[lr * SXS + c]) = h;
    }

    #pragma unroll
    for (int it = 0; it < 8; it++) {
        int idx = t + it * 128;
        int r = idx >> 4, c4 = idx & 15;
        *reinterpret_cast<float4*>(&sW[r * 64 + c4 * 4]) =
            *reinterpret_cast<const float4*>(&W2[(size_t)r * 64 + c4 * 4]);
    }
    __syncthreads();

    unsigned long long acc2[4][4] = {};
    gemm_tile8(sX, sW, acc2, tx, ty);
    #pragma unroll
    for (int i = 0; i < 4; i++) {
        int r = row0 + ty * 4 + i;
        if (r < n) store_half8(g_sh2, r, tx, acc2[i], g_dinv[r]);   // fold dinv[r]
    }
}

// ---------- final gather on g_sh2 (pre-scaled) -> x_out ----------
__global__ __launch_bounds__(256) void k_gather_final(
    const float* __restrict__ b, float* __restrict__ out, int n)
{
    int v = blockIdx.x * 16 + (threadIdx.x >> 4);
    if (v >= n) return;
    int c = (threadIdx.x & 15) * 4;

    int beg = g_off[v];
    int end = g_off[v + 1];

    float dv = g_dinv[v];
    float4 acc = ld_half4(g_sh2, v, c);   // self-loop, already dinv[v]-scaled

    int j = beg;
    for (; j + 4 <= end; j += 4) {
        int u0 = __ldg(&g_csr[j]);
        int u1 = __ldg(&g_csr[j + 1]);
        int u2 = __ldg(&g_csr[j + 2]);
        int u3 = __ldg(&g_csr[j + 3]);
        float4 a0 = ld_half4(g_sh2, u0, c);
        float4 a1 = ld_half4(g_sh2, u1, c);
        float4 a2 = ld_half4(g_sh2, u2, c);
        float4 a3 = ld_half4(g_sh2, u3, c);
        acc.x += (a0.x + a1.x) + (a2.x + a3.x);
        acc.y += (a0.y + a1.y) + (a2.y + a3.y);
        acc.z += (a0.z + a1.z) + (a2.z + a3.z);
        acc.w += (a0.w + a1.w) + (a2.w + a3.w);
    }
    for (; j < end; j++) {
        int u = __ldg(&g_csr[j]);
        float4 a = ld_half4(g_sh2, u, c);
        acc.x += a.x; acc.y += a.y; acc.z += a.z; acc.w += a.w;
    }

    float4 bb = *reinterpret_cast<const float4*>(&b[c]);
    float4 o;
    o.x = fmaxf(fmaf(dv, acc.x, bb.x), 0.f);
    o.y = fmaxf(fmaf(dv, acc.y, bb.y), 0.f);
    o.z = fmaxf(fmaf(dv, acc.z, bb.z), 0.f);
    o.w = fmaxf(fmaf(dv, acc.w, bb.w), 0.f);
    *reinterpret_cast<float4*>(&out[(size_t)v * HD + c]) = o;
}

extern "C" void kernel_launch(void* const* d_in, const int* in_sizes, int n_in,
                              void* d_out, int out_size) {
    const float* x     = (const float*)d_in[0];
    const int*   eidx  = (const int*)  d_in[1];
    const float* W_pre = (const float*)d_in[2];
    const float* b_pre = (const float*)d_in[3];
    const float* W1    = (const float*)d_in[4];
    const float* b1    = (const float*)d_in[5];
    const float* W2    = (const float*)d_in[6];
    const float* b2    = (const float*)d_in[7];
    float* out = (float*)d_out;

    int n = in_sizes[0] / 128;
    int e = in_sizes[1] / 2;
    const int* src = eidx;
    const int* dst = eidx + e;

    float* x_out = out;
    float* ori_x = out + (size_t)n * HD;

    const int T = 256;
    int gb_n  = (n + T - 1) / T;
    int gb_e  = (e + T - 1) / T;
    int gb_g  = (n + 63) / 64;
    int nb    = (n + SCAN_B - 1) / SCAN_B;
    int gb_a  = (n + 15) / 16;
    int gb_sc = (n * (HD / 4) + T - 1) / T;

    // Fork: CSR build on side stream; fused GEMM on main (capture) stream.
    // Host stream/event objects created per call, intentionally not destroyed.
    cudaStream_t s2;
    cudaStreamCreateWithFlags(&s2, cudaStreamNonBlocking);
    cudaEvent_t evFork, evA;
    cudaEventCreateWithFlags(&evFork, cudaEventDisableTiming);
    cudaEventCreateWithFlags(&evA, cudaEventDisableTiming);

    cudaEventRecord(evFork, 0);
    cudaStreamWaitEvent(s2, evFork, 0);

    // branch A (s2): CSR build + dinv
    k_zero_deg<<<gb_n, T, 0, s2>>>(n);
    k_count<<<gb_e, T, 0, s2>>>(dst, e);
    k_scan1<<<nb, SCAN_B, 0, s2>>>(n);
    k_scan3<<<nb, SCAN_B, 0, s2>>>(n, e);
    k_fill<<<gb_e, T, 0, s2>>>(src, dst, e);
    cudaEventRecord(evA, s2);

    // branch B (main): fused pre-linear + layer-1 GEMM
    k_fused_pre_w1<<<gb_g, 128>>>(x, W_pre, b_pre, W1, ori_x, n);

    // join; fold dinv into g_sh; graph-dependent fused layer + final gather
    cudaStreamWaitEvent(0, evA, 0);
    k_scale_sh<<<gb_sc, T>>>(n);
    k_fused_gather_w2<<<gb_g, 128>>>(b1, W2, n);
    k_gather_final<<<gb_a, T>>>(b2, x_out, n);
}

// round 14
// speedup vs baseline: 1.3328x; 1.3328x over previous
#include <cuda_runtime.h>
#include <cuda_fp16.h>

#define HD 64
static const int NMAX = 100000;
static const int EMAX = 1200000;

// Scratch (allocation-free per harness rules)
__device__ int    g_deg[NMAX];
__device__ int    g_off[NMAX + 1];
__device__ int    g_cur[NMAX];
__device__ int    g_part[1024];
__device__ int    g_csr[EMAX];
__device__ float  g_dinv[NMAX];
__device__ __half g_sh[NMAX * HD];    // fp16 layer-1 messages (unscaled)
__device__ __half g_sh2[NMAX * HD];   // fp16 layer-2 messages (dinv[r] folded at store)

// ---------- packed f32x2 helpers ----------
__device__ __forceinline__ unsigned long long pack2(float a) {
    unsigned long long r;
    asm("mov.b64 %0, {%1, %1};" : "=l"(r) : "f"(a));
    return r;
}
__device__ __forceinline__ void fma2(unsigned long long& d,
                                     unsigned long long a,
                                     unsigned long long b) {
    asm("fma.rn.f32x2 %0, %1, %2, %0;" : "+l"(d) : "l"(a), "l"(b));
}
__device__ __forceinline__ float2 unpack2(unsigned long long v) {
    float2 u;
    asm("mov.b64 {%0, %1}, %2;" : "=f"(u.x), "=f"(u.y) : "l"(v));
    return u;
}

// ---------- graph preprocessing (branch A, overlapped) ----------
__global__ void k_zero_deg(int n) {
    int i = blockIdx.x * blockDim.x + threadIdx.x;
    if (i < n) g_deg[i] = 0;
}

__global__ void k_count(const int* __restrict__ dst, int e) {
    int i = blockIdx.x * blockDim.x + threadIdx.x;
    if (i < e) {
        int d = dst[i];
        if (d >= 0 && d < NMAX) atomicAdd(&g_deg[d], 1);
    }
}

#define SCAN_B 512
__global__ __launch_bounds__(SCAN_B) void k_scan1(int n) {
    __shared__ int warp_sums[SCAN_B / 32];
    int i = blockIdx.x * SCAN_B + threadIdx.x;
    int v = (i < n) ? g_deg[i] : 0;
    int lane = threadIdx.x & 31, wid = threadIdx.x >> 5;

    int s = v;
    #pragma unroll
    for (int d = 1; d < 32; d <<= 1) {
        int t = __shfl_up_sync(0xffffffffu, s, d);
        if (lane >= d) s += t;
    }
    if (lane == 31) warp_sums[wid] = s;
    __syncthreads();
    if (wid == 0) {
        int ws = (lane < SCAN_B / 32) ? warp_sums[lane] : 0;
        #pragma unroll
        for (int d = 1; d < SCAN_B / 32; d <<= 1) {
            int t = __shfl_up_sync(0xffffffffu, ws, d);
            if (lane >= d) ws += t;
        }
        if (lane < SCAN_B / 32) warp_sums[lane] = ws;
    }
    __syncthreads();
    int base = (wid > 0) ? warp_sums[wid - 1] : 0;
    int incl = base + s;
    if (i < n) g_off[i] = incl - v;
    if (threadIdx.x == SCAN_B - 1) g_part[blockIdx.x] = incl;
}

// fused pass 2+3: reduce g_part[0..blockIdx) inline, finalize offsets/cursors/dinv
__global__ __launch_bounds__(SCAN_B) void k_scan3(int n, int e) {
    __shared__ int warp_red[SCAN_B / 32];
    __shared__ int s_base;
    int b = blockIdx.x;
    int tid = threadIdx.x, lane = tid & 31, wid = tid >> 5;

    int v = (tid < b) ? g_part[tid] : 0;
    #pragma unroll
    for (int d = 16; d > 0; d >>= 1) v += __shfl_down_sync(0xffffffffu, v, d);
    if (lane == 0) warp_red[wid] = v;
    __syncthreads();
    if (wid == 0) {
        int t = (lane < SCAN_B / 32) ? warp_red[lane] : 0;
        #pragma unroll
        for (int d = 8; d > 0; d >>= 1) t += __shfl_down_sync(0xffffffffu, t, d);
        if (lane == 0) s_base = t;
    }
    __syncthreads();
    int base = s_base;

    int i = b * SCAN_B + tid;
    if (i < n) {
        int o = g_off[i] + base;
        g_off[i] = o;
        g_cur[i] = o;
        g_dinv[i] = rsqrtf((float)(g_deg[i] + 1));
    }
    if (i == 0) g_off[n] = e;
}

__global__ void k_fill(const int* __restrict__ src, const int* __restrict__ dst, int e) {
    int i = blockIdx.x * blockDim.x + threadIdx.x;
    if (i < e) {
        int d = dst[i];
        if (d >= 0 && d < NMAX) {
            int pos = atomicAdd(&g_cur[d], 1);
            if (pos >= 0 && pos < EMAX) g_csr[pos] = src[i];
        }
    }
}

// ---------- helpers ----------
#define SXS 68   // padded row stride for sX

__device__ __forceinline__ float4 ld_half4(const __half* base, int u, int c) {
    uint2 p = *reinterpret_cast<const uint2*>(&base[(size_t)u * HD + c]);
    __half2 a = *reinterpret_cast<__half2*>(&p.x);
    __half2 b = *reinterpret_cast<__half2*>(&p.y);
    float2 fa = __half22float2(a), fb = __half22float2(b);
    return make_float4(fa.x, fa.y, fb.x, fb.y);
}

// 8 halfs (16B) at base[u*64 + c] -> two float4
__device__ __forceinline__ void ld_half8(const __half* base, int u, int c,
                                         float4& lo, float4& hi) {
    uint4 p = *reinterpret_cast<const uint4*>(&base[(size_t)u * HD + c]);
    __half2 a = *reinterpret_cast<__half2*>(&p.x);
    __half2 b = *reinterpret_cast<__half2*>(&p.y);
    __half2 cc = *reinterpret_cast<__half2*>(&p.z);
    __half2 d = *reinterpret_cast<__half2*>(&p.w);
    float2 fa = __half22float2(a), fb = __half22float2(b);
    float2 fc = __half22float2(cc), fd = __half22float2(d);
    lo = make_float4(fa.x, fa.y, fb.x, fb.y);
    hi = make_float4(fc.x, fc.y, fd.x, fd.y);
}

// sX[64 x 64 fp32, stride SXS] @ sW[64 x 64] -> acc (thread (tx,ty): rows ty*4+i, col-quad tx)
__device__ __forceinline__ void gemm_tile(const float* sX, const float* sW,
                                          unsigned long long acc[4][2],
                                          int tx, int ty) {
    #pragma unroll 8
    for (int k = 0; k < 64; k++) {
        ulonglong2 w = *reinterpret_cast<const ulonglong2*>(&sW[k * 64 + tx * 4]);
        #pragma unroll
        for (int i = 0; i < 4; i++) {
            unsigned long long ap = pack2(sX[(ty * 4 + i) * SXS + k]);
            fma2(acc[i][0], ap, w.x);
            fma2(acc[i][1], ap, w.y);
        }
    }
}

__device__ __forceinline__ void store_half4_scaled(__half* base, int r, int tx,
                                                   unsigned long long a0,
                                                   unsigned long long a1, float s) {
    float2 lo = unpack2(a0);
    float2 hi = unpack2(a1);
    __half2 h0 = __floats2half2_rn(lo.x * s, lo.y * s);
    __half2 h1 = __floats2half2_rn(hi.x * s, hi.y * s);
    uint2 o;
    o.x = *reinterpret_cast<unsigned int*>(&h0);
    o.y = *reinterpret_cast<unsigned int*>(&h1);
    *reinterpret_cast<uint2*>(&base[(size_t)r * HD + tx * 4]) = o;
}

// ---------- fused: (x @ W_pre + b_pre) -> ori_x ; tile @ W1 -> g_sh ----------
__global__ __launch_bounds__(256) void k_fused_pre_w1(
    const float* __restrict__ x, const float* __restrict__ Wp,
    const float* __restrict__ bp, const float* __restrict__ W1,
    float* __restrict__ ori_x, int n)
{
    __shared__ float sX[64 * SXS];
    __shared__ float sW[64 * 64];
    int row0 = blockIdx.x * 64;
    int t = threadIdx.x;
    int tx = t & 15, ty = t >> 4;

    unsigned long long acc[4][2] = {};

    for (int kc = 0; kc < 2; kc++) {
        if (kc) __syncthreads();
        #pragma unroll
        for (int it = 0; it < 4; it++) {
            int idx = t + it * 256;
            int r = idx >> 4, c4 = idx & 15;
            float4 v = make_float4(0.f, 0.f, 0.f, 0.f);
            if (row0 + r < n)
                v = *reinterpret_cast<const float4*>(&x[(size_t)(row0 + r) * 128 + kc * 64 + c4 * 4]);
            *reinterpret_cast<float4*>(&sX[r * SXS + c4 * 4]) = v;
            *reinterpret_cast<float4*>(&sW[r * 64 + c4 * 4]) =
                *reinterpret_cast<const float4*>(&Wp[(size_t)(kc * 64 + r) * 64 + c4 * 4]);
        }
        __syncthreads();
        gemm_tile(sX, sW, acc, tx, ty);
    }

    // epilogue 1: +bias, write ori_x, park tile in sX, load W1
    __syncthreads();
    float4 bb = *reinterpret_cast<const float4*>(&bp[tx * 4]);
    #pragma unroll
    for (int i = 0; i < 4; i++) {
        float2 lo = unpack2(acc[i][0]);
        float2 hi = unpack2(acc[i][1]);
        float4 o = make_float4(lo.x + bb.x, lo.y + bb.y, hi.x + bb.z, hi.y + bb.w);
        int r = row0 + ty * 4 + i;
        *reinterpret_cast<float4*>(&sX[(ty * 4 + i) * SXS + tx * 4]) = o;
        if (r < n)
            *reinterpret_cast<float4*>(&ori_x[(size_t)r * HD + tx * 4]) = o;
    }
    #pragma unroll
    for (int it = 0; it < 4; it++) {
        int idx = t + it * 256;
        int r = idx >> 4, c4 = idx & 15;
        *reinterpret_cast<float4*>(&sW[r * 64 + c4 * 4]) =
            *reinterpret_cast<const float4*>(&W1[(size_t)r * 64 + c4 * 4]);
    }
    __syncthreads();

    // phase 2: g_sh = tile @ W1 (fp16)
    unsigned long long acc2[4][2] = {};
    gemm_tile(sX, sW, acc2, tx, ty);
    #pragma unroll
    for (int i = 0; i < 4; i++) {
        int r = row0 + ty * 4 + i;
        if (r < n) store_half4_scaled(g_sh, r, tx, acc2[i][0], acc2[i][1], 1.0f);
    }
}

// ---------- fused: gather layer-1 -> h (smem) ; h @ W2 -> g_sh2 (dinv[r]-scaled) ----------
__global__ __launch_bounds__(256) void k_fused_gather_w2(
    const float* __restrict__ b1, const float* __restrict__ W2, int n)
{
    __shared__ float sX[64 * SXS];
    __shared__ float sW[64 * 64];
    int row0 = blockIdx.x * 64;
    int t = threadIdx.x;
    int tx = t & 15, ty = t >> 4;
    int grp = t >> 4;
    int c = (t & 15) * 4;

    float4 bb1 = *reinterpret_cast<const float4*>(&b1[c]);
    #pragma unroll
    for (int it = 0; it < 4; it++) {
        int lr = grp + it * 16;
        int v = row0 + lr;
        float4 h = make_float4(0.f, 0.f, 0.f, 0.f);
        if (v < n) {
            int beg = g_off[v];
            int end = g_off[v + 1];
            float dv = g_dinv[v];
            float4 sv = ld_half4(g_sh, v, c);
            float4 acc = make_float4(dv * sv.x, dv * sv.y, dv * sv.z, dv * sv.w);

            int j = beg;
            for (; j + 4 <= end; j += 4) {
                int u0 = __ldg(&g_csr[j]);
                int u1 = __ldg(&g_csr[j + 1]);
                int u2 = __ldg(&g_csr[j + 2]);
                int u3 = __ldg(&g_csr[j + 3]);
                float d0 = __ldg(&g_dinv[u0]);
                float d1 = __ldg(&g_dinv[u1]);
                float d2 = __ldg(&g_dinv[u2]);
                float d3 = __ldg(&g_dinv[u3]);
                float4 a0 = ld_half4(g_sh, u0, c);
                float4 a1 = ld_half4(g_sh, u1, c);
                float4 a2 = ld_half4(g_sh, u2, c);
                float4 a3 = ld_half4(g_sh, u3, c);
                acc.x += (d0 * a0.x + d1 * a1.x) + (d2 * a2.x + d3 * a3.x);
                acc.y += (d0 * a0.y + d1 * a1.y) + (d2 * a2.y + d3 * a3.y);
                acc.z += (d0 * a0.z + d1 * a1.z) + (d2 * a2.z + d3 * a3.z);
                acc.w += (d0 * a0.w + d1 * a1.w) + (d2 * a2.w + d3 * a3.w);
            }
            for (; j < end; j++) {
                int u = __ldg(&g_csr[j]);
                float d = __ldg(&g_dinv[u]);
                float4 a = ld_half4(g_sh, u, c);
                acc.x += d * a.x; acc.y += d * a.y; acc.z += d * a.z; acc.w += d * a.w;
            }
            h.x = fmaxf(fmaf(dv, acc.x, bb1.x), 0.f);
            h.y = fmaxf(fmaf(dv, acc.y, bb1.y), 0.f);
            h.z = fmaxf(fmaf(dv, acc.z, bb1.z), 0.f);
            h.w = fmaxf(fmaf(dv, acc.w, bb1.w), 0.f);
        }
        *reinterpret_cast<float4*>(&sX[lr * SXS + c]) = h;
    }

    #pragma unroll
    for (int it = 0; it < 4; it++) {
        int idx = t + it * 256;
        int r = idx >> 4, c4 = idx & 15;
        *reinterpret_cast<float4*>(&sW[r * 64 + c4 * 4]) =
            *reinterpret_cast<const float4*>(&W2[(size_t)r * 64 + c4 * 4]);
    }
    __syncthreads();

    unsigned long long acc2[4][2] = {};
    gemm_tile(sX, sW, acc2, tx, ty);
    #pragma unroll
    for (int i = 0; i < 4; i++) {
        int r = row0 + ty * 4 + i;
        if (r < n)
            store_half4_scaled(g_sh2, r, tx, acc2[i][0], acc2[i][1], g_dinv[r]);
    }
}

// ---------- final gather on pre-scaled g_sh2 -> x_out ----------
// 8 threads/node, 16B loads: halves message-load instruction count.
__global__ __launch_bounds__(256) void k_gather_final(
    const float* __restrict__ b, float* __restrict__ out, int n)
{
    int v = blockIdx.x * 32 + (threadIdx.x >> 3);
    if (v >= n) return;
    int c = (threadIdx.x & 7) * 8;

    int beg = g_off[v];
    int end = g_off[v + 1];

    float dv = g_dinv[v];
    float4 aL, aH;
    ld_half8(g_sh2, v, c, aL, aH);   // self-loop, already dinv[v]-scaled
    float4 accL = aL, accH = aH;

    int j = beg;
    for (; j + 4 <= end; j += 4) {
        int u0 = __ldg(&g_csr[j]);
        int u1 = __ldg(&g_csr[j + 1]);
        int u2 = __ldg(&g_csr[j + 2]);
        int u3 = __ldg(&g_csr[j + 3]);
        float4 l0, h0, l1, h1, l2, h2, l3, h3;
        ld_half8(g_sh2, u0, c, l0, h0);
        ld_half8(g_sh2, u1, c, l1, h1);
        ld_half8(g_sh2, u2, c, l2, h2);
        ld_half8(g_sh2, u3, c, l3, h3);
        accL.x += (l0.x + l1.x) + (l2.x + l3.x);
        accL.y += (l0.y + l1.y) + (l2.y + l3.y);
        accL.z += (l0.z + l1.z) + (l2.z + l3.z);
        accL.w += (l0.w + l1.w) + (l2.w + l3.w);
        accH.x += (h0.x + h1.x) + (h2.x + h3.x);
        accH.y += (h0.y + h1.y) + (h2.y + h3.y);
        accH.z += (h0.z + h1.z) + (h2.z + h3.z);
        accH.w += (h0.w + h1.w) + (h2.w + h3.w);
    }
    for (; j < end; j++) {
        int u = __ldg(&g_csr[j]);
        float4 l, h;
        ld_half8(g_sh2, u, c, l, h);
        accL.x += l.x; accL.y += l.y; accL.z += l.z; accL.w += l.w;
        accH.x += h.x; accH.y += h.y; accH.z += h.z; accH.w += h.w;
    }

    float4 bbL = *reinterpret_cast<const float4*>(&b[c]);
    float4 bbH = *reinterpret_cast<const float4*>(&b[c + 4]);
    float4 oL, oH;
    oL.x = fmaxf(fmaf(dv, accL.x, bbL.x), 0.f);
    oL.y = fmaxf(fmaf(dv, accL.y, bbL.y), 0.f);
    oL.z = fmaxf(fmaf(dv, accL.z, bbL.z), 0.f);
    oL.w = fmaxf(fmaf(dv, accL.w, bbL.w), 0.f);
    oH.x = fmaxf(fmaf(dv, accH.x, bbH.x), 0.f);
    oH.y = fmaxf(fmaf(dv, accH.y, bbH.y), 0.f);
    oH.z = fmaxf(fmaf(dv, accH.z, bbH.z), 0.f);
    oH.w = fmaxf(fmaf(dv, accH.w, bbH.w), 0.f);
    *reinterpret_cast<float4*>(&out[(size_t)v * HD + c]) = oL;
    *reinterpret_cast<float4*>(&out[(size_t)v * HD + c + 4]) = oH;
}

extern "C" void kernel_launch(void* const* d_in, const int* in_sizes, int n_in,
                              void* d_out, int out_size) {
    const float* x     = (const float*)d_in[0];
    const int*   eidx  = (const int*)  d_in[1];
    const float* W_pre = (const float*)d_in[2];
    const float* b_pre = (const float*)d_in[3];
    const float* W1    = (const float*)d_in[4];
    const float* b1    = (const float*)d_in[5];
    const float* W2    = (const float*)d_in[6];
    const float* b2    = (const float*)d_in[7];
    float* out = (float*)d_out;

    int n = in_sizes[0] / 128;
    int e = in_sizes[1] / 2;
    const int* src = eidx;
    const int* dst = eidx + e;

    float* x_out = out;
    float* ori_x = out + (size_t)n * HD;

    const int T = 256;
    int gb_n = (n + T - 1) / T;
    int gb_e = (e + T - 1) / T;
    int gb_g = (n + 63) / 64;
    int nb   = (n + SCAN_B - 1) / SCAN_B;
    int gb_f = (n + 31) / 32;

    // Fork: CSR build on side stream; fused GEMM on main (capture) stream.
    // Host stream/event objects created per call, intentionally not destroyed.
    cudaStream_t s2;
    cudaStreamCreateWithFlags(&s2, cudaStreamNonBlocking);
    cudaEvent_t evFork, evA;
    cudaEventCreateWithFlags(&evFork, cudaEventDisableTiming);
    cudaEventCreateWithFlags(&evA, cudaEventDisableTiming);

    cudaEventRecord(evFork, 0);
    cudaStreamWaitEvent(s2, evFork, 0);

    // branch A (s2): CSR build + dinv
    k_zero_deg<<<gb_n, T, 0, s2>>>(n);
    k_count<<<gb_e, T, 0, s2>>>(dst, e);
    k_scan1<<<nb, SCAN_B, 0, s2>>>(n);
    k_scan3<<<nb, SCAN_B, 0, s2>>>(n, e);
    k_fill<<<gb_e, T, 0, s2>>>(src, dst, e);
    cudaEventRecord(evA, s2);

    // branch B (main): fused pre-linear + layer-1 GEMM
    k_fused_pre_w1<<<gb_g, T>>>(x, W_pre, b_pre, W1, ori_x, n);

    // join, then graph-dependent fused layer + final gather
    cudaStreamWaitEvent(0, evA, 0);
    k_fused_gather_w2<<<gb_g, T>>>(b1, W2, n);
    k_gather_final<<<gb_f, T>>>(b2, x_out, n);
}